// round 14
// baseline (speedup 1.0000x reference)
#include <cuda_runtime.h>
#include <cuda_bf16.h>
#include <cuda_fp16.h>
#include <cstdint>

#define N_NODES 100000
#define N_EDGES 1600000
#define FEAT    128

#define SCAN_BLK   512
#define SCAN_NBLK  ((N_NODES + SCAN_BLK - 1) / SCAN_BLK)   // 196

// ---------------- device scratch (no allocations allowed) ----------------
__device__ float g_bufB[N_NODES * FEAT];                   // fp32 GEMM output (next layer input)
__device__ __half g_h16[N_NODES * FEAT];                   // fp16 gather copy (layers 2-3)
__device__ __nv_bfloat16 g_ahi[N_NODES * FEAT];            // agg output, bf16 hi
__device__ __nv_bfloat16 g_alo[N_NODES * FEAT];            // agg output, bf16 lo
__device__ int   g_histcnt[N_NODES];                       // degree histogram (zero invariant)
__device__ int   g_edgerank[N_EDGES];                      // per-edge rank within dst
__device__ int   g_rowstart[N_NODES + 1];
__device__ float g_invdeg[N_NODES];
__device__ int   g_csr_src[N_EDGES];                       // stores src*32 (pre-scaled)
__device__ int   g_aggval[SCAN_NBLK];
__device__ int   g_count;                                  // grid-sync counter (zero invariant)
__device__ __nv_bfloat16 g_whi[3 * FEAT * FEAT];           // [n][k] (K contiguous) = col-major B
__device__ __nv_bfloat16 g_wlo[3 * FEAT * FEAT];

// ---------------- helpers ----------------
__device__ __forceinline__ uint32_t smem_u32(const void* p) {
    uint32_t a;
    asm("{ .reg .u64 t; cvta.to.shared.u64 t, %1; cvt.u32.u64 %0, t; }" : "=r"(a) : "l"(p));
    return a;
}
__device__ __forceinline__ void cp_async16(uint32_t dst, const void* src) {
    asm volatile("cp.async.cg.shared.global [%0], [%1], 16;" :: "r"(dst), "l"(src) : "memory");
}
__device__ __forceinline__ void cp_commit() {
    asm volatile("cp.async.commit_group;" ::: "memory");
}
__device__ __forceinline__ void cp_wait0() {
    asm volatile("cp.async.wait_group 0;" ::: "memory");
}
__device__ __forceinline__ void ldmatrix_x4(uint32_t* r, uint32_t addr) {
    asm volatile("ldmatrix.sync.aligned.m8n8.x4.shared.b16 {%0,%1,%2,%3}, [%4];"
                 : "=r"(r[0]), "=r"(r[1]), "=r"(r[2]), "=r"(r[3]) : "r"(addr));
}
__device__ __forceinline__ void mma16816(float* c, const uint32_t* a, const uint32_t* b) {
    asm volatile("mma.sync.aligned.m16n8k16.row.col.f32.bf16.bf16.f32 "
                 "{%0,%1,%2,%3}, {%4,%5,%6,%7}, {%8,%9}, {%0,%1,%2,%3};"
                 : "+f"(c[0]), "+f"(c[1]), "+f"(c[2]), "+f"(c[3])
                 : "r"(a[0]), "r"(a[1]), "r"(a[2]), "r"(a[3]), "r"(b[0]), "r"(b[1]));
}
__device__ __forceinline__ float4 h16_to_f4(uint2 u) {
    __half2 a = *reinterpret_cast<__half2*>(&u.x);
    __half2 b = *reinterpret_cast<__half2*>(&u.y);
    float2 fa = __half22float2(a);
    float2 fb = __half22float2(b);
    return make_float4(fa.x, fa.y, fb.x, fb.y);
}

// ---------------- CSR build ----------------
// hist: counts degrees AND records each edge's rank within its dst node.
__global__ void hist_kernel(const int4* __restrict__ dst4) {
    int t = blockIdx.x * blockDim.x + threadIdx.x;
    if (t < N_EDGES / 4) {
        int4 d = __ldg(&dst4[t]);
        int4 rk;
        rk.x = atomicAdd(&g_histcnt[d.x], 1);
        rk.y = atomicAdd(&g_histcnt[d.y], 1);
        rk.z = atomicAdd(&g_histcnt[d.z], 1);
        rk.w = atomicAdd(&g_histcnt[d.w], 1);
        reinterpret_cast<int4*>(g_edgerank)[t] = rk;
    }
}

// single-kernel device-wide exclusive scan over degrees (196 co-resident blocks)
__global__ void scan_fused_kernel() {
    int b = blockIdx.x, tid = threadIdx.x;
    int i = b * SCAN_BLK + tid;
    int d = (i < N_NODES) ? g_histcnt[i] : 0;
    if (i < N_NODES) g_histcnt[i] = 0;     // restore zero invariant
    int lane = tid & 31, w = tid >> 5;

    int v = d;
    #pragma unroll
    for (int off = 1; off < 32; off <<= 1) {
        int n = __shfl_up_sync(0xFFFFFFFFu, v, off);
        if (lane >= off) v += n;
    }
    __shared__ int ws[16];
    if (lane == 31) ws[w] = v;
    __syncthreads();
    if (tid < 16) {
        int s = ws[tid];
        #pragma unroll
        for (int off = 1; off < 16; off <<= 1) {
            int n = __shfl_up_sync(0xFFFFu, s, off);
            if (tid >= off) s += n;
        }
        ws[tid] = s;
    }
    __syncthreads();
    int incl = ((w > 0) ? ws[w - 1] : 0) + v;
    int T = ws[15];

    if (tid == 0) {
        g_aggval[b] = T;
        __threadfence();
        atomicAdd(&g_count, 1);
        while (atomicAdd(&g_count, 0) < SCAN_NBLK) { }
    }
    __syncthreads();

    int contrib = 0;
    if (tid < b) contrib = *((volatile int*)&g_aggval[tid]);
    #pragma unroll
    for (int off = 16; off > 0; off >>= 1) contrib += __shfl_down_sync(0xFFFFFFFFu, contrib, off);
    __shared__ int rs[16];
    if (lane == 0) rs[w] = contrib;
    __syncthreads();
    __shared__ int baseS;
    if (tid < 16) {
        int s = rs[tid];
        #pragma unroll
        for (int off = 8; off > 0; off >>= 1) s += __shfl_down_sync(0xFFFFu, s, off);
        if (tid == 0) baseS = s;
    }
    __syncthreads();
    int base = baseS;

    int excl = base + incl - d;
    if (i < N_NODES) {
        g_rowstart[i] = excl;
        g_invdeg[i]   = 1.0f / fmaxf((float)d, 1.0f);
    }
    if (b == SCAN_NBLK - 1 && tid == SCAN_BLK - 1) g_rowstart[N_NODES] = base + incl;

    // final block resets the counter for the next call
    __syncthreads();
    if (tid == 0) {
        __threadfence();
        int done = atomicAdd(&g_count, 1);
        if (done == 2 * SCAN_NBLK - 1) atomicExch(&g_count, 0);
    }
}

// scatter without atomics: position = rowstart[dst] + recorded rank
__global__ void scatter_kernel(const int4* __restrict__ src4, const int4* __restrict__ dst4) {
    int t = blockIdx.x * blockDim.x + threadIdx.x;
    if (t < N_EDGES / 4) {
        int4 s = __ldg(&src4[t]);
        int4 d = __ldg(&dst4[t]);
        int4 rk = reinterpret_cast<const int4*>(g_edgerank)[t];
        g_csr_src[__ldg(&g_rowstart[d.x]) + rk.x] = s.x << 5;
        g_csr_src[__ldg(&g_rowstart[d.y]) + rk.y] = s.y << 5;
        g_csr_src[__ldg(&g_rowstart[d.z]) + rk.z] = s.z << 5;
        g_csr_src[__ldg(&g_rowstart[d.w]) + rk.w] = s.w << 5;
    }
}

// ---------------- weight prep: fp32 W[k][n] -> bf16 hi/lo in [n][k] ----------------
__global__ void convw_kernel(const float* __restrict__ W1, const float* __restrict__ W2,
                             const float* __restrict__ W3) {
    int i = blockIdx.x * blockDim.x + threadIdx.x;
    if (i >= 3 * FEAT * FEAT) return;
    int l = i >> 14, r = i & 16383;
    int n = r >> 7, k = r & 127;
    const float* W = (l == 0) ? W1 : ((l == 1) ? W2 : W3);
    float v = W[k * FEAT + n];
    __nv_bfloat16 h = __float2bfloat16(v);
    g_whi[i] = h;
    g_wlo[i] = __float2bfloat16(v - __bfloat162float(h));
}

// ---------------- aggregation helpers ----------------
__device__ __forceinline__ void agg_epilogue(int warp, int lane, float4 acc, float4 self) {
    float w = g_invdeg[warp];
    float4 o;
    o.x = self.x + acc.x * w;
    o.y = self.y + acc.y * w;
    o.z = self.z + acc.z * w;
    o.w = self.w + acc.w * w;

    __nv_bfloat162 h0 = __floats2bfloat162_rn(o.x, o.y);
    __nv_bfloat162 h1 = __floats2bfloat162_rn(o.z, o.w);
    float2 f0 = __bfloat1622float2(h0);
    float2 f1 = __bfloat1622float2(h1);
    __nv_bfloat162 l0 = __floats2bfloat162_rn(o.x - f0.x, o.y - f0.y);
    __nv_bfloat162 l1 = __floats2bfloat162_rn(o.z - f1.x, o.w - f1.y);
    uint2 hv, lv;
    hv.x = *reinterpret_cast<uint32_t*>(&h0);
    hv.y = *reinterpret_cast<uint32_t*>(&h1);
    lv.x = *reinterpret_cast<uint32_t*>(&l0);
    lv.y = *reinterpret_cast<uint32_t*>(&l1);
    reinterpret_cast<uint2*>(g_ahi)[(size_t)warp * 32 + lane] = hv;
    reinterpret_cast<uint2*>(g_alo)[(size_t)warp * 32 + lane] = lv;
}

// layer 1: gather fp32 x rows (exact input)
__global__ void agg_kernel(const float4* __restrict__ hself) {
    int warp = (blockIdx.x * blockDim.x + threadIdx.x) >> 5;
    if (warp >= N_NODES) return;
    int lane = threadIdx.x & 31;

    int s = g_rowstart[warp];
    int e = g_rowstart[warp + 1];

    float4 acc = make_float4(0.f, 0.f, 0.f, 0.f);
    int i = s;
    for (; i + 4 <= e; i += 4) {
        int i0 = __ldg(&g_csr_src[i + 0]);
        int i1 = __ldg(&g_csr_src[i + 1]);
        int i2 = __ldg(&g_csr_src[i + 2]);
        int i3 = __ldg(&g_csr_src[i + 3]);
        float4 v0 = __ldg(&hself[i0 + lane]);
        float4 v1 = __ldg(&hself[i1 + lane]);
        float4 v2 = __ldg(&hself[i2 + lane]);
        float4 v3 = __ldg(&hself[i3 + lane]);
        acc.x += (v0.x + v1.x) + (v2.x + v3.x);
        acc.y += (v0.y + v1.y) + (v2.y + v3.y);
        acc.z += (v0.z + v1.z) + (v2.z + v3.z);
        acc.w += (v0.w + v1.w) + (v2.w + v3.w);
    }
    for (; i < e; i++) {
        int s0 = __ldg(&g_csr_src[i]);
        float4 v = __ldg(&hself[s0 + lane]);
        acc.x += v.x; acc.y += v.y; acc.z += v.z; acc.w += v.w;
    }

    float4 self = __ldg(&hself[(size_t)warp * 32 + lane]);
    agg_epilogue(warp, lane, acc, self);
}

// layers 2-3: gather fp16 rows (half the bytes/wavefronts); self term fp32
__global__ void agg16_kernel(const float4* __restrict__ hself) {
    int warp = (blockIdx.x * blockDim.x + threadIdx.x) >> 5;
    if (warp >= N_NODES) return;
    int lane = threadIdx.x & 31;

    const uint2* h16 = reinterpret_cast<const uint2*>(g_h16);   // 32 x 8B per row

    int s = g_rowstart[warp];
    int e = g_rowstart[warp + 1];

    float4 acc = make_float4(0.f, 0.f, 0.f, 0.f);
    int i = s;
    for (; i + 4 <= e; i += 4) {
        int i0 = __ldg(&g_csr_src[i + 0]);
        int i1 = __ldg(&g_csr_src[i + 1]);
        int i2 = __ldg(&g_csr_src[i + 2]);
        int i3 = __ldg(&g_csr_src[i + 3]);
        float4 v0 = h16_to_f4(__ldg(&h16[i0 + lane]));
        float4 v1 = h16_to_f4(__ldg(&h16[i1 + lane]));
        float4 v2 = h16_to_f4(__ldg(&h16[i2 + lane]));
        float4 v3 = h16_to_f4(__ldg(&h16[i3 + lane]));
        acc.x += (v0.x + v1.x) + (v2.x + v3.x);
        acc.y += (v0.y + v1.y) + (v2.y + v3.y);
        acc.z += (v0.z + v1.z) + (v2.z + v3.z);
        acc.w += (v0.w + v1.w) + (v2.w + v3.w);
    }
    for (; i < e; i++) {
        int s0 = __ldg(&g_csr_src[i]);
        float4 v = h16_to_f4(__ldg(&h16[s0 + lane]));
        acc.x += v.x; acc.y += v.y; acc.z += v.z; acc.w += v.w;
    }

    float4 self = __ldg(&hself[(size_t)warp * 32 + lane]);
    agg_epilogue(warp, lane, acc, self);
}

// ---------------- persistent HMMA GEMM: out[M,128] = [relu](A @ W + b) ----------------
// 256 threads, warp grid 4m x 2n, warp tile 32x64; B via ldmatrix.x4 (paired n-groups).
// Optional fp16 dual-write (gather table for the NEXT layer's aggregation).
#define APITCH 136
#define TILE_E (128 * APITCH)
#define GEMM_SMEM_BYTES (6 * TILE_E * 2 + 512)

__global__ void __launch_bounds__(256, 1)
mma_gemm_kernel(const __nv_bfloat16* __restrict__ Ahi,
                const __nv_bfloat16* __restrict__ Alo,
                const __nv_bfloat16* __restrict__ whi,
                const __nv_bfloat16* __restrict__ wlo,
                const float* __restrict__ bias,
                float* __restrict__ out, __half2* __restrict__ out16,
                int M, int do_relu) {
    extern __shared__ __nv_bfloat16 sm[];
    __nv_bfloat16* sWhi = sm;
    __nv_bfloat16* sWlo = sm + TILE_E;
    __nv_bfloat16* sA   = sm + 2 * TILE_E;
    float* sBias = reinterpret_cast<float*>(sm + 6 * TILE_E);

    const int tid  = threadIdx.x;
    const int lane = tid & 31;
    const int wid  = tid >> 5;
    const int NT   = (M + 127) / 128;
    const int step = gridDim.x;

    {
        const uint4* wh4 = reinterpret_cast<const uint4*>(whi);
        const uint4* wl4 = reinterpret_cast<const uint4*>(wlo);
        for (int idx = tid; idx < 2048; idx += 256) {
            int r = idx >> 4, c16 = idx & 15;
            int eoff = r * APITCH + c16 * 8;
            *reinterpret_cast<uint4*>(sWhi + eoff) = __ldg(&wh4[idx]);
            *reinterpret_cast<uint4*>(sWlo + eoff) = __ldg(&wl4[idx]);
        }
        if (tid < 32)
            reinterpret_cast<float4*>(sBias)[tid] = __ldg(&reinterpret_cast<const float4*>(bias)[tid]);
    }

    const uint32_t sAaddr = smem_u32(sA);
    const uint32_t wmBase = smem_u32(sWhi);

    auto issue_tile = [&](int tile, int buf) {
        int row0 = tile * 128;
        int rows = min(128, M - row0);
        int nchunk = rows * 16;
        const char* srcHi = reinterpret_cast<const char*>(Ahi + (size_t)row0 * 128);
        const char* srcLo = reinterpret_cast<const char*>(Alo + (size_t)row0 * 128);
        uint32_t dstHi = sAaddr + (uint32_t)(buf * 2) * (TILE_E * 2);
        uint32_t dstLo = dstHi + TILE_E * 2;
        for (int idx = tid; idx < nchunk; idx += 256) {
            int r = idx >> 4, c = idx & 15;
            uint32_t doff = (uint32_t)(r * (APITCH * 2) + c * 16);
            int soff = r * 256 + c * 16;
            cp_async16(dstHi + doff, srcHi + soff);
            cp_async16(dstLo + doff, srcLo + soff);
        }
        cp_commit();
    };

    const int wm = wid & 3;
    const int wn = wid >> 2;
    const uint32_t aRowOff = (uint32_t)(((wm * 32 + (lane & 15)) * APITCH + (lane >> 4) * 8) * 2);
    const uint32_t bRowOff = (uint32_t)(((wn * 64 + (lane & 7) + ((lane >> 4) << 3)) * APITCH
                                         + ((lane >> 3) & 1) * 8) * 2);

    int t0 = blockIdx.x;
    if (t0 < NT) issue_tile(t0, 0);

    int it = 0;
    for (int t = t0; t < NT; t += step, it++) {
        int buf = it & 1;
        cp_wait0();
        __syncthreads();
        int nt = t + step;
        if (nt < NT) issue_tile(nt, buf ^ 1);

        float acc[2][8][4];
        #pragma unroll
        for (int a = 0; a < 2; a++)
            #pragma unroll
            for (int b = 0; b < 8; b++)
                #pragma unroll
                for (int c = 0; c < 4; c++) acc[a][b][c] = 0.f;

        uint32_t aHiB = sAaddr + (uint32_t)(buf * 2) * (TILE_E * 2);
        uint32_t aLoB = aHiB + TILE_E * 2;

        #pragma unroll
        for (int pass = 0; pass < 3; pass++) {
            uint32_t aAddr = ((pass == 2) ? aLoB : aHiB) + aRowOff;
            uint32_t bAddr = wmBase + ((pass == 1) ? (uint32_t)(TILE_E * 2) : 0u) + bRowOff;

            #pragma unroll
            for (int kk = 0; kk < 8; kk++) {
                uint32_t a0[4], a1[4];
                ldmatrix_x4(a0, aAddr + kk * 32);
                ldmatrix_x4(a1, aAddr + 16 * APITCH * 2 + kk * 32);
                #pragma unroll
                for (int tp = 0; tp < 4; tp++) {
                    uint32_t bb[4];
                    ldmatrix_x4(bb, bAddr + tp * 16 * APITCH * 2 + kk * 32);
                    mma16816(acc[0][tp * 2 + 0], a0, bb + 0);
                    mma16816(acc[1][tp * 2 + 0], a1, bb + 0);
                    mma16816(acc[0][tp * 2 + 1], a0, bb + 2);
                    mma16816(acc[1][tp * 2 + 1], a1, bb + 2);
                }
            }
        }

        int row0 = t * 128;
        int rows = min(128, M - row0);
        #pragma unroll
        for (int tm = 0; tm < 2; tm++) {
            int rbase = wm * 32 + tm * 16 + (lane >> 2);
            #pragma unroll
            for (int half = 0; half < 2; half++) {
                int r = rbase + half * 8;
                if (r < rows) {
                    float* orow = out + (size_t)(row0 + r) * 128;
                    __half2* hrow = out16 ? (out16 + (size_t)(row0 + r) * 64) : nullptr;
                    #pragma unroll
                    for (int tn = 0; tn < 8; tn++) {
                        int c = wn * 64 + tn * 8 + (lane & 3) * 2;
                        float2 o;
                        o.x = acc[tm][tn][half * 2 + 0] + sBias[c + 0];
                        o.y = acc[tm][tn][half * 2 + 1] + sBias[c + 1];
                        if (do_relu) { o.x = fmaxf(o.x, 0.f); o.y = fmaxf(o.y, 0.f); }
                        *reinterpret_cast<float2*>(orow + c) = o;
                        if (hrow) hrow[c >> 1] = __floats2half2_rn(o.x, o.y);
                    }
                }
            }
        }
    }
}

// ---------------- launch ----------------
extern "C" void kernel_launch(void* const* d_in, const int* in_sizes, int n_in,
                              void* d_out, int out_size) {
    const float* x        = (const float*)d_in[0];
    const float* W1       = (const float*)d_in[1];
    const float* b1       = (const float*)d_in[2];
    const float* W2       = (const float*)d_in[3];
    const float* b2       = (const float*)d_in[4];
    const float* W3       = (const float*)d_in[5];
    const float* b3       = (const float*)d_in[6];
    const int*   edge_src = (const int*)d_in[7];
    const int*   edge_dst = (const int*)d_in[8];
    float* out = (float*)d_out;

    (void)in_sizes; (void)n_in; (void)out_size;

    cudaFuncSetAttribute(mma_gemm_kernel,
                         cudaFuncAttributeMaxDynamicSharedMemorySize, GEMM_SMEM_BYTES);

    int numSM = 148;
    cudaDeviceGetAttribute(&numSM, cudaDevAttrMultiProcessorCount, 0);

    float* bufB;
    __nv_bfloat16 *whi, *wlo, *ahi, *alo;
    __half* h16;
    cudaGetSymbolAddress((void**)&bufB, g_bufB);
    cudaGetSymbolAddress((void**)&whi, g_whi);
    cudaGetSymbolAddress((void**)&wlo, g_wlo);
    cudaGetSymbolAddress((void**)&ahi, g_ahi);
    cudaGetSymbolAddress((void**)&alo, g_alo);
    cudaGetSymbolAddress((void**)&h16, g_h16);
    __half2* h16_2 = (__half2*)h16;

    const int M = N_NODES;
    const int edge4Blocks = (N_EDGES / 4 + 255) / 256;
    const int aggBlocks   = (N_NODES * 32 + 127) / 128;

    // CSR build
    hist_kernel<<<edge4Blocks, 256>>>((const int4*)edge_dst);            // 0
    scan_fused_kernel<<<SCAN_NBLK, SCAN_BLK>>>();                        // 1
    scatter_kernel<<<edge4Blocks, 256>>>((const int4*)edge_src,
                                         (const int4*)edge_dst);         // 2
    // layer 1 (fp32 gather of x)
    agg_kernel<<<aggBlocks, 128>>>((const float4*)x);                    // 3 (profiled)
    convw_kernel<<<(3 * FEAT * FEAT + 255) / 256, 256>>>(W1, W2, W3);    // 4
    mma_gemm_kernel<<<numSM, 256, GEMM_SMEM_BYTES>>>(ahi, alo, whi, wlo, b1, bufB, h16_2, M, 1);
    // layer 2 (fp16 gather)
    agg16_kernel<<<aggBlocks, 128>>>((const float4*)bufB);
    mma_gemm_kernel<<<numSM, 256, GEMM_SMEM_BYTES>>>(ahi, alo, whi + FEAT * FEAT, wlo + FEAT * FEAT, b2, bufB, h16_2, M, 1);
    // layer 3 (fp16 gather; fp32 output only)
    agg16_kernel<<<aggBlocks, 128>>>((const float4*)bufB);
    mma_gemm_kernel<<<numSM, 256, GEMM_SMEM_BYTES>>>(ahi, alo, whi + 2 * FEAT * FEAT, wlo + 2 * FEAT * FEAT, b3, out, (half2*)nullptr, M, 0);
}

// round 15
// speedup vs baseline: 1.0466x; 1.0466x over previous
#include <cuda_runtime.h>
#include <cuda_bf16.h>
#include <cstdint>

#define N_NODES 100000
#define N_EDGES 1600000
#define FEAT    128

#define SCAN_BLK   512
#define SCAN_NBLK  ((N_NODES + SCAN_BLK - 1) / SCAN_BLK)   // 196

// ---------------- device scratch (no allocations allowed) ----------------
__device__ float g_bufB[N_NODES * FEAT];                   // fp32 GEMM output (next layer input)
__device__ __nv_bfloat16 g_ahi[N_NODES * FEAT];            // agg output, bf16 hi
__device__ __nv_bfloat16 g_alo[N_NODES * FEAT];            // agg output, bf16 lo
__device__ int   g_histcnt[N_NODES];                       // degree histogram (zero invariant)
__device__ int   g_edgerank[N_EDGES];                      // per-edge rank within dst
__device__ int   g_rowstart[N_NODES + 1];
__device__ float g_invdeg[N_NODES];
__device__ int   g_csr_src[N_EDGES];                       // stores src*32 (pre-scaled)
__device__ int   g_aggval[SCAN_NBLK];
__device__ int   g_count;                                  // grid-sync counter (zero invariant)
__device__ __nv_bfloat16 g_whi[3 * FEAT * FEAT];           // [n][k] (K contiguous) = col-major B
__device__ __nv_bfloat16 g_wlo[3 * FEAT * FEAT];

// ---------------- helpers ----------------
__device__ __forceinline__ uint32_t smem_u32(const void* p) {
    uint32_t a;
    asm("{ .reg .u64 t; cvta.to.shared.u64 t, %1; cvt.u32.u64 %0, t; }" : "=r"(a) : "l"(p));
    return a;
}
__device__ __forceinline__ void cp_async16(uint32_t dst, const void* src) {
    asm volatile("cp.async.cg.shared.global [%0], [%1], 16;" :: "r"(dst), "l"(src) : "memory");
}
__device__ __forceinline__ void cp_commit() {
    asm volatile("cp.async.commit_group;" ::: "memory");
}
__device__ __forceinline__ void cp_wait0() {
    asm volatile("cp.async.wait_group 0;" ::: "memory");
}
__device__ __forceinline__ void ldmatrix_x4(uint32_t* r, uint32_t addr) {
    asm volatile("ldmatrix.sync.aligned.m8n8.x4.shared.b16 {%0,%1,%2,%3}, [%4];"
                 : "=r"(r[0]), "=r"(r[1]), "=r"(r[2]), "=r"(r[3]) : "r"(addr));
}
__device__ __forceinline__ void mma16816(float* c, const uint32_t* a, const uint32_t* b) {
    asm volatile("mma.sync.aligned.m16n8k16.row.col.f32.bf16.bf16.f32 "
                 "{%0,%1,%2,%3}, {%4,%5,%6,%7}, {%8,%9}, {%0,%1,%2,%3};"
                 : "+f"(c[0]), "+f"(c[1]), "+f"(c[2]), "+f"(c[3])
                 : "r"(a[0]), "r"(a[1]), "r"(a[2]), "r"(a[3]), "r"(b[0]), "r"(b[1]));
}

// ---------------- CSR build ----------------
// hist: counts degrees AND records each edge's rank within its dst node.
__global__ void hist_kernel(const int4* __restrict__ dst4) {
    int t = blockIdx.x * blockDim.x + threadIdx.x;
    if (t < N_EDGES / 4) {
        int4 d = __ldg(&dst4[t]);
        int4 rk;
        rk.x = atomicAdd(&g_histcnt[d.x], 1);
        rk.y = atomicAdd(&g_histcnt[d.y], 1);
        rk.z = atomicAdd(&g_histcnt[d.z], 1);
        rk.w = atomicAdd(&g_histcnt[d.w], 1);
        reinterpret_cast<int4*>(g_edgerank)[t] = rk;
    }
}

// single-kernel device-wide exclusive scan over degrees (196 co-resident blocks)
__global__ void scan_fused_kernel() {
    int b = blockIdx.x, tid = threadIdx.x;
    int i = b * SCAN_BLK + tid;
    int d = (i < N_NODES) ? g_histcnt[i] : 0;
    if (i < N_NODES) g_histcnt[i] = 0;     // restore zero invariant
    int lane = tid & 31, w = tid >> 5;

    int v = d;
    #pragma unroll
    for (int off = 1; off < 32; off <<= 1) {
        int n = __shfl_up_sync(0xFFFFFFFFu, v, off);
        if (lane >= off) v += n;
    }
    __shared__ int ws[16];
    if (lane == 31) ws[w] = v;
    __syncthreads();
    if (tid < 16) {
        int s = ws[tid];
        #pragma unroll
        for (int off = 1; off < 16; off <<= 1) {
            int n = __shfl_up_sync(0xFFFFu, s, off);
            if (tid >= off) s += n;
        }
        ws[tid] = s;
    }
    __syncthreads();
    int incl = ((w > 0) ? ws[w - 1] : 0) + v;
    int T = ws[15];

    if (tid == 0) {
        g_aggval[b] = T;
        __threadfence();
        atomicAdd(&g_count, 1);
        while (atomicAdd(&g_count, 0) < SCAN_NBLK) { }
    }
    __syncthreads();

    int contrib = 0;
    if (tid < b) contrib = *((volatile int*)&g_aggval[tid]);
    #pragma unroll
    for (int off = 16; off > 0; off >>= 1) contrib += __shfl_down_sync(0xFFFFFFFFu, contrib, off);
    __shared__ int rs[16];
    if (lane == 0) rs[w] = contrib;
    __syncthreads();
    __shared__ int baseS;
    if (tid < 16) {
        int s = rs[tid];
        #pragma unroll
        for (int off = 8; off > 0; off >>= 1) s += __shfl_down_sync(0xFFFFu, s, off);
        if (tid == 0) baseS = s;
    }
    __syncthreads();
    int base = baseS;

    int excl = base + incl - d;
    if (i < N_NODES) {
        g_rowstart[i] = excl;
        g_invdeg[i]   = 1.0f / fmaxf((float)d, 1.0f);
    }
    if (b == SCAN_NBLK - 1 && tid == SCAN_BLK - 1) g_rowstart[N_NODES] = base + incl;

    // final block resets the counter for the next call
    __syncthreads();
    if (tid == 0) {
        __threadfence();
        int done = atomicAdd(&g_count, 1);
        if (done == 2 * SCAN_NBLK - 1) atomicExch(&g_count, 0);
    }
}

// scatter without atomics: position = rowstart[dst] + recorded rank
__global__ void scatter_kernel(const int4* __restrict__ src4, const int4* __restrict__ dst4) {
    int t = blockIdx.x * blockDim.x + threadIdx.x;
    if (t < N_EDGES / 4) {
        int4 s = __ldg(&src4[t]);
        int4 d = __ldg(&dst4[t]);
        int4 rk = reinterpret_cast<const int4*>(g_edgerank)[t];
        g_csr_src[__ldg(&g_rowstart[d.x]) + rk.x] = s.x << 5;
        g_csr_src[__ldg(&g_rowstart[d.y]) + rk.y] = s.y << 5;
        g_csr_src[__ldg(&g_rowstart[d.z]) + rk.z] = s.z << 5;
        g_csr_src[__ldg(&g_rowstart[d.w]) + rk.w] = s.w << 5;
    }
}

// ---------------- weight prep: fp32 W[k][n] -> bf16 hi/lo in [n][k] ----------------
__global__ void convw_kernel(const float* __restrict__ W1, const float* __restrict__ W2,
                             const float* __restrict__ W3) {
    int i = blockIdx.x * blockDim.x + threadIdx.x;
    if (i >= 3 * FEAT * FEAT) return;
    int l = i >> 14, r = i & 16383;
    int n = r >> 7, k = r & 127;
    const float* W = (l == 0) ? W1 : ((l == 1) ? W2 : W3);
    float v = W[k * FEAT + n];
    __nv_bfloat16 h = __float2bfloat16(v);
    g_whi[i] = h;
    g_wlo[i] = __float2bfloat16(v - __bfloat162float(h));
}

// ---------------- aggregation: (h + mean_neighbors) split to bf16 hi/lo tables ----------------
// 128-thread blocks; pre-scaled gather indices; fp32 gather (fp16 falsified R6/R14).
__global__ void agg_kernel(const float4* __restrict__ hself) {
    int warp = (blockIdx.x * blockDim.x + threadIdx.x) >> 5;
    if (warp >= N_NODES) return;
    int lane = threadIdx.x & 31;

    int s = g_rowstart[warp];
    int e = g_rowstart[warp + 1];

    float4 acc = make_float4(0.f, 0.f, 0.f, 0.f);
    int i = s;
    for (; i + 4 <= e; i += 4) {
        int i0 = __ldg(&g_csr_src[i + 0]);
        int i1 = __ldg(&g_csr_src[i + 1]);
        int i2 = __ldg(&g_csr_src[i + 2]);
        int i3 = __ldg(&g_csr_src[i + 3]);
        float4 v0 = __ldg(&hself[i0 + lane]);
        float4 v1 = __ldg(&hself[i1 + lane]);
        float4 v2 = __ldg(&hself[i2 + lane]);
        float4 v3 = __ldg(&hself[i3 + lane]);
        acc.x += (v0.x + v1.x) + (v2.x + v3.x);
        acc.y += (v0.y + v1.y) + (v2.y + v3.y);
        acc.z += (v0.z + v1.z) + (v2.z + v3.z);
        acc.w += (v0.w + v1.w) + (v2.w + v3.w);
    }
    for (; i < e; i++) {
        int s0 = __ldg(&g_csr_src[i]);
        float4 v = __ldg(&hself[s0 + lane]);
        acc.x += v.x; acc.y += v.y; acc.z += v.z; acc.w += v.w;
    }

    float w = g_invdeg[warp];
    float4 self = __ldg(&hself[(size_t)warp * 32 + lane]);
    float4 o;
    o.x = self.x + acc.x * w;
    o.y = self.y + acc.y * w;
    o.z = self.z + acc.z * w;
    o.w = self.w + acc.w * w;

    __nv_bfloat162 h0 = __floats2bfloat162_rn(o.x, o.y);
    __nv_bfloat162 h1 = __floats2bfloat162_rn(o.z, o.w);
    float2 f0 = __bfloat1622float2(h0);
    float2 f1 = __bfloat1622float2(h1);
    __nv_bfloat162 l0 = __floats2bfloat162_rn(o.x - f0.x, o.y - f0.y);
    __nv_bfloat162 l1 = __floats2bfloat162_rn(o.z - f1.x, o.w - f1.y);
    uint2 hv, lv;
    hv.x = *reinterpret_cast<uint32_t*>(&h0);
    hv.y = *reinterpret_cast<uint32_t*>(&h1);
    lv.x = *reinterpret_cast<uint32_t*>(&l0);
    lv.y = *reinterpret_cast<uint32_t*>(&l1);
    reinterpret_cast<uint2*>(g_ahi)[(size_t)warp * 32 + lane] = hv;
    reinterpret_cast<uint2*>(g_alo)[(size_t)warp * 32 + lane] = lv;
}

// ---------------- persistent HMMA GEMM: out[M,128] = [relu](A @ W + b) ----------------
// 256 threads, warp grid 4m x 2n, warp tile 32x64.
// Interleaved kk-loop: load aHi/aLo + wHi/wLo fragments ONCE per kk (12 ldmatrix
// instead of 18 across the 3 hi/lo passes); all 48 MMAs issued per kk.
#define APITCH 136
#define TILE_E (128 * APITCH)
#define GEMM_SMEM_BYTES (6 * TILE_E * 2 + 512)

__global__ void __launch_bounds__(256, 1)
mma_gemm_kernel(const __nv_bfloat16* __restrict__ Ahi,
                const __nv_bfloat16* __restrict__ Alo,
                const __nv_bfloat16* __restrict__ whi,
                const __nv_bfloat16* __restrict__ wlo,
                const float* __restrict__ bias,
                float* __restrict__ out, int M, int do_relu) {
    extern __shared__ __nv_bfloat16 sm[];
    __nv_bfloat16* sWhi = sm;
    __nv_bfloat16* sWlo = sm + TILE_E;
    __nv_bfloat16* sA   = sm + 2 * TILE_E;
    float* sBias = reinterpret_cast<float*>(sm + 6 * TILE_E);

    const int tid  = threadIdx.x;
    const int lane = tid & 31;
    const int wid  = tid >> 5;
    const int NT   = (M + 127) / 128;
    const int step = gridDim.x;

    {
        const uint4* wh4 = reinterpret_cast<const uint4*>(whi);
        const uint4* wl4 = reinterpret_cast<const uint4*>(wlo);
        for (int idx = tid; idx < 2048; idx += 256) {
            int r = idx >> 4, c16 = idx & 15;
            int eoff = r * APITCH + c16 * 8;
            *reinterpret_cast<uint4*>(sWhi + eoff) = __ldg(&wh4[idx]);
            *reinterpret_cast<uint4*>(sWlo + eoff) = __ldg(&wl4[idx]);
        }
        if (tid < 32)
            reinterpret_cast<float4*>(sBias)[tid] = __ldg(&reinterpret_cast<const float4*>(bias)[tid]);
    }

    const uint32_t sAaddr = smem_u32(sA);
    const uint32_t wmBase = smem_u32(sWhi);

    auto issue_tile = [&](int tile, int buf) {
        int row0 = tile * 128;
        int rows = min(128, M - row0);
        int nchunk = rows * 16;
        const char* srcHi = reinterpret_cast<const char*>(Ahi + (size_t)row0 * 128);
        const char* srcLo = reinterpret_cast<const char*>(Alo + (size_t)row0 * 128);
        uint32_t dstHi = sAaddr + (uint32_t)(buf * 2) * (TILE_E * 2);
        uint32_t dstLo = dstHi + TILE_E * 2;
        for (int idx = tid; idx < nchunk; idx += 256) {
            int r = idx >> 4, c = idx & 15;
            uint32_t doff = (uint32_t)(r * (APITCH * 2) + c * 16);
            int soff = r * 256 + c * 16;
            cp_async16(dstHi + doff, srcHi + soff);
            cp_async16(dstLo + doff, srcLo + soff);
        }
        cp_commit();
    };

    const int wm = wid & 3;
    const int wn = wid >> 2;
    const uint32_t aRowOff = (uint32_t)(((wm * 32 + (lane & 15)) * APITCH + (lane >> 4) * 8) * 2);
    const uint32_t bRowOff = (uint32_t)(((wn * 64 + (lane & 7) + ((lane >> 4) << 3)) * APITCH
                                         + ((lane >> 3) & 1) * 8) * 2);

    int t0 = blockIdx.x;
    if (t0 < NT) issue_tile(t0, 0);

    int it = 0;
    for (int t = t0; t < NT; t += step, it++) {
        int buf = it & 1;
        cp_wait0();
        __syncthreads();
        int nt = t + step;
        if (nt < NT) issue_tile(nt, buf ^ 1);

        float acc[2][8][4];
        #pragma unroll
        for (int a = 0; a < 2; a++)
            #pragma unroll
            for (int b = 0; b < 8; b++)
                #pragma unroll
                for (int c = 0; c < 4; c++) acc[a][b][c] = 0.f;

        uint32_t aHiAddr = sAaddr + (uint32_t)(buf * 2) * (TILE_E * 2) + aRowOff;
        uint32_t aLoAddr = aHiAddr + TILE_E * 2;
        uint32_t bHiAddr = wmBase + bRowOff;
        uint32_t bLoAddr = bHiAddr + (uint32_t)(TILE_E * 2);

        #pragma unroll
        for (int kk = 0; kk < 8; kk++) {
            uint32_t ah0[4], ah1[4], al0[4], al1[4];
            ldmatrix_x4(ah0, aHiAddr + kk * 32);
            ldmatrix_x4(ah1, aHiAddr + 16 * APITCH * 2 + kk * 32);
            ldmatrix_x4(al0, aLoAddr + kk * 32);
            ldmatrix_x4(al1, aLoAddr + 16 * APITCH * 2 + kk * 32);
            #pragma unroll
            for (int tp = 0; tp < 4; tp++) {
                uint32_t bh[4], bl[4];
                ldmatrix_x4(bh, bHiAddr + tp * 16 * APITCH * 2 + kk * 32);
                ldmatrix_x4(bl, bLoAddr + tp * 16 * APITCH * 2 + kk * 32);
                // D += aHi*wHi + aHi*wLo + aLo*wHi
                mma16816(acc[0][tp * 2 + 0], ah0, bh + 0);
                mma16816(acc[1][tp * 2 + 0], ah1, bh + 0);
                mma16816(acc[0][tp * 2 + 1], ah0, bh + 2);
                mma16816(acc[1][tp * 2 + 1], ah1, bh + 2);
                mma16816(acc[0][tp * 2 + 0], ah0, bl + 0);
                mma16816(acc[1][tp * 2 + 0], ah1, bl + 0);
                mma16816(acc[0][tp * 2 + 1], ah0, bl + 2);
                mma16816(acc[1][tp * 2 + 1], ah1, bl + 2);
                mma16816(acc[0][tp * 2 + 0], al0, bh + 0);
                mma16816(acc[1][tp * 2 + 0], al1, bh + 0);
                mma16816(acc[0][tp * 2 + 1], al0, bh + 2);
                mma16816(acc[1][tp * 2 + 1], al1, bh + 2);
            }
        }

        int row0 = t * 128;
        int rows = min(128, M - row0);
        #pragma unroll
        for (int tm = 0; tm < 2; tm++) {
            int rbase = wm * 32 + tm * 16 + (lane >> 2);
            #pragma unroll
            for (int half = 0; half < 2; half++) {
                int r = rbase + half * 8;
                if (r < rows) {
                    float* orow = out + (size_t)(row0 + r) * 128;
                    #pragma unroll
                    for (int tn = 0; tn < 8; tn++) {
                        int c = wn * 64 + tn * 8 + (lane & 3) * 2;
                        float2 o;
                        o.x = acc[tm][tn][half * 2 + 0] + sBias[c + 0];
                        o.y = acc[tm][tn][half * 2 + 1] + sBias[c + 1];
                        if (do_relu) { o.x = fmaxf(o.x, 0.f); o.y = fmaxf(o.y, 0.f); }
                        *reinterpret_cast<float2*>(orow + c) = o;
                    }
                }
            }
        }
    }
}

// ---------------- launch ----------------
extern "C" void kernel_launch(void* const* d_in, const int* in_sizes, int n_in,
                              void* d_out, int out_size) {
    const float* x        = (const float*)d_in[0];
    const float* W1       = (const float*)d_in[1];
    const float* b1       = (const float*)d_in[2];
    const float* W2       = (const float*)d_in[3];
    const float* b2       = (const float*)d_in[4];
    const float* W3       = (const float*)d_in[5];
    const float* b3       = (const float*)d_in[6];
    const int*   edge_src = (const int*)d_in[7];
    const int*   edge_dst = (const int*)d_in[8];
    float* out = (float*)d_out;

    (void)in_sizes; (void)n_in; (void)out_size;

    cudaFuncSetAttribute(mma_gemm_kernel,
                         cudaFuncAttributeMaxDynamicSharedMemorySize, GEMM_SMEM_BYTES);

    int numSM = 148;
    cudaDeviceGetAttribute(&numSM, cudaDevAttrMultiProcessorCount, 0);

    float* bufB;
    __nv_bfloat16 *whi, *wlo, *ahi, *alo;
    cudaGetSymbolAddress((void**)&bufB, g_bufB);
    cudaGetSymbolAddress((void**)&whi, g_whi);
    cudaGetSymbolAddress((void**)&wlo, g_wlo);
    cudaGetSymbolAddress((void**)&ahi, g_ahi);
    cudaGetSymbolAddress((void**)&alo, g_alo);

    const int M = N_NODES;
    const int edge4Blocks = (N_EDGES / 4 + 255) / 256;
    const int aggBlocks   = (N_NODES * 32 + 127) / 128;

    // CSR build
    hist_kernel<<<edge4Blocks, 256>>>((const int4*)edge_dst);            // 0
    scan_fused_kernel<<<SCAN_NBLK, SCAN_BLK>>>();                        // 1
    scatter_kernel<<<edge4Blocks, 256>>>((const int4*)edge_src,
                                         (const int4*)edge_dst);         // 2
    // layer 1
    agg_kernel<<<aggBlocks, 128>>>((const float4*)x);                    // 3 (profiled)
    convw_kernel<<<(3 * FEAT * FEAT + 255) / 256, 256>>>(W1, W2, W3);    // 4
    mma_gemm_kernel<<<numSM, 256, GEMM_SMEM_BYTES>>>(ahi, alo, whi, wlo, b1, bufB, M, 1);
    // layer 2
    agg_kernel<<<aggBlocks, 128>>>((const float4*)bufB);
    mma_gemm_kernel<<<numSM, 256, GEMM_SMEM_BYTES>>>(ahi, alo, whi + FEAT * FEAT, wlo + FEAT * FEAT, b2, bufB, M, 1);
    // layer 3
    agg_kernel<<<aggBlocks, 128>>>((const float4*)bufB);
    mma_gemm_kernel<<<numSM, 256, GEMM_SMEM_BYTES>>>(ahi, alo, whi + 2 * FEAT * FEAT, wlo + 2 * FEAT * FEAT, b3, out, M, 0);
}